// round 15
// baseline (speedup 1.0000x reference)
#include <cuda_runtime.h>
#include <cuda.h>
#include <cuda_fp16.h>
#include <math.h>
#include <stdint.h>

// Problem constants
#define BSZ   1024
#define NPTS  128
#define LOG2PI_F 1.8378770664093453f
#define LOG2E_F  1.4426950408889634f
#define LOG1P_HALF 0.40546510810816438f

// Output layout offsets
#define OFF_SAMPLED 0
#define OFF_GEN     524288
#define OFF_REAL    655360
#define OFF_LOSSA   786432
#define OFF_LOSSB   917504

// 2-way split: a = h + l'*2^-11  (residual ~2^-22)
#define SC_L 4.8828125e-4f            // 2^-11

#define ACT_PLANE 262144              // halves per activation plane (1024*256)
#define W_LAYER   (2 * 256 * 256)     // halves per layer of split weights

// mlp6 smem: 3 W slots (64KB each) + 2 act buffers (16KB each) + 3 mbars
#define SLOT_BYTES 65536
#define SM_ACT0    196608
#define SM_ACT1    212992
#define SM_MBAR    229376
#define SM_TOTAL   229440

typedef unsigned long long u64;

// Scratch (128B aligned for TMA)
__device__ __align__(128) __half g_Act[2 * ACT_PLANE];   // split latents (2 planes)
__device__ __align__(128) __half g_Wsplit[6 * W_LAYER];  // [L][split][n][k]
__device__ float g_mu[BSZ * 256];

// ---------------------------------------------------------------------------
// helpers
// ---------------------------------------------------------------------------
__device__ __forceinline__ uint32_t cvta_smem(const void* p) {
    uint32_t a;
    asm("{ .reg .u64 t; cvta.to.shared.u64 t, %1; cvt.u32.u64 %0, t; }"
        : "=r"(a) : "l"(p));
    return a;
}
__device__ __forceinline__ void ldsm4(uint32_t* r, uint32_t addr) {
    asm volatile("ldmatrix.sync.aligned.m8n8.x4.shared.b16 {%0,%1,%2,%3}, [%4];"
                 : "=r"(r[0]), "=r"(r[1]), "=r"(r[2]), "=r"(r[3]) : "r"(addr));
}
__device__ __forceinline__ void mma16816(float* d, const uint32_t* a, const uint32_t* b) {
    asm("mma.sync.aligned.m16n8k16.row.col.f32.f16.f16.f32 "
        "{%0,%1,%2,%3}, {%4,%5,%6,%7}, {%8,%9}, {%0,%1,%2,%3};"
        : "+f"(d[0]), "+f"(d[1]), "+f"(d[2]), "+f"(d[3])
        : "r"(a[0]), "r"(a[1]), "r"(a[2]), "r"(a[3]), "r"(b[0]), "r"(b[1]));
}
__device__ __forceinline__ void mbar_init(uint32_t a, uint32_t cnt) {
    asm volatile("mbarrier.init.shared.b64 [%0], %1;" :: "r"(a), "r"(cnt) : "memory");
}
__device__ __forceinline__ void mbar_expect_tx(uint32_t a, uint32_t bytes) {
    asm volatile("mbarrier.arrive.expect_tx.shared.b64 _, [%0], %1;"
                 :: "r"(a), "r"(bytes) : "memory");
}
__device__ __forceinline__ void mbar_wait(uint32_t mbar, uint32_t par) {
    asm volatile(
        "{\n\t.reg .pred P1;\n\t"
        "WAIT_LOOP_%=:\n\t"
        "mbarrier.try_wait.parity.shared::cta.b64 P1, [%0], %1, 0x989680;\n\t"
        "@P1 bra.uni WAIT_DONE_%=;\n\t"
        "bra.uni WAIT_LOOP_%=;\n\t"
        "WAIT_DONE_%=:\n\t}"
        :: "r"(mbar), "r"(par) : "memory");
}
__device__ __forceinline__ void tma3d(uint32_t sdst, const CUtensorMap* tm,
                                      int x, int y, int z, uint32_t mbar) {
    asm volatile(
        "cp.async.bulk.tensor.3d.shared::cta.global.tile.mbarrier::complete_tx::bytes "
        "[%0], [%1, {%2, %3, %4}], [%5];"
        :: "r"(sdst), "l"(tm), "r"(x), "r"(y), "r"(z), "r"(mbar) : "memory");
}
__device__ __forceinline__ float ex2f(float x) {
    float y;
    asm("ex2.approx.f32 %0, %1;" : "=f"(y) : "f"(x));
    return y;
}
__device__ __forceinline__ void split2(float a, __half& h, __half& l) {
    h = __float2half_rn(a);
    float r1 = a - __half2float(h);
    l = __float2half_rn(r1 * 2048.0f);
}
__device__ __forceinline__ uint32_t pack2(__half a, __half b) {
    __half2 h = __halves2half2(a, b);
    return *(uint32_t*)&h;
}
__device__ __forceinline__ uint32_t swz(uint32_t c, uint32_t r) {
    return (c & 24u) | ((c ^ r) & 7u);
}
// packed f32x2 ops
__device__ __forceinline__ u64 packf2(float lo, float hi) {
    u64 r;
    asm("mov.b64 %0, {%1, %2};" : "=l"(r) : "f"(lo), "f"(hi));
    return r;
}
__device__ __forceinline__ void unpackf2(u64 v, float& lo, float& hi) {
    asm("mov.b64 {%0, %1}, %2;" : "=f"(lo), "=f"(hi) : "l"(v));
}
__device__ __forceinline__ u64 add2(u64 a, u64 b) {
    u64 r;
    asm("add.rn.f32x2 %0, %1, %2;" : "=l"(r) : "l"(a), "l"(b));
    return r;
}
__device__ __forceinline__ u64 mul2(u64 a, u64 b) {
    u64 r;
    asm("mul.rn.f32x2 %0, %1, %2;" : "=l"(r) : "l"(a), "l"(b));
    return r;
}
__device__ __forceinline__ u64 fma2(u64 a, u64 b, u64 c) {
    u64 r;
    asm("fma.rn.f32x2 %0, %1, %2, %3;" : "=l"(r) : "l"(a), "l"(b), "l"(c));
    return r;
}

// ---------------------------------------------------------------------------
// prep: g_Wsplit[L][s][n][k] fp16 2-split of W_L^T (L=5 is Wp reshaped)
// ---------------------------------------------------------------------------
__global__ __launch_bounds__(256) void prep_weights(
    const float* __restrict__ W0, const float* __restrict__ W1,
    const float* __restrict__ W2, const float* __restrict__ W3,
    const float* __restrict__ W4, const float* __restrict__ Wp)
{
    __shared__ float stage[256][9];
    const int L  = blockIdx.y;
    const int n0 = blockIdx.x * 8;
    const int t  = threadIdx.x;

    {
        const int k = t;
        if (L < 5) {
            const float* W = (L == 0) ? W0 : (L == 1) ? W1 : (L == 2) ? W2
                           : (L == 3) ? W3 : W4;
            float4 v0 = *(const float4*)&W[k * 256 + n0];
            float4 v1 = *(const float4*)&W[k * 256 + n0 + 4];
            stage[k][0] = v0.x; stage[k][1] = v0.y; stage[k][2] = v0.z; stage[k][3] = v0.w;
            stage[k][4] = v1.x; stage[k][5] = v1.y; stage[k][6] = v1.z; stage[k][7] = v1.w;
        } else {
#pragma unroll
            for (int j = 0; j < 8; j++) {
                int n = n0 + j;
                stage[k][j] = Wp[(n >> 1) * 512 + k * 2 + (n & 1)];
            }
        }
    }
    __syncthreads();
    {
        const int nl = t >> 5;
        const int k0 = (t & 31) * 8;
        __half h[8], l[8];
#pragma unroll
        for (int i = 0; i < 8; i++)
            split2(stage[k0 + i][nl], h[i], l[i]);
        const int n = n0 + nl;
        __half* base = g_Wsplit + (size_t)L * W_LAYER;
        uint4 v;
        v.x = pack2(h[0], h[1]); v.y = pack2(h[2], h[3]);
        v.z = pack2(h[4], h[5]); v.w = pack2(h[6], h[7]);
        *(uint4*)(base + (0 * 256 + n) * 256 + k0) = v;
        v.x = pack2(l[0], l[1]); v.y = pack2(l[2], l[3]);
        v.z = pack2(l[4], l[5]); v.w = pack2(l[6], l[7]);
        *(uint4*)(base + (1 * 256 + n) * 256 + k0) = v;
    }
}

// ---------------------------------------------------------------------------
// prep latents: fp32 [1024][256] -> 2 fp16 split planes
// ---------------------------------------------------------------------------
__global__ __launch_bounds__(256) void prep_latents(
    const float* __restrict__ L, __half* __restrict__ out)
{
    int idx = (blockIdx.x * 256 + threadIdx.x) * 4;
    float4 v = *(const float4*)(L + idx);
    __half h[4], l[4];
    split2(v.x, h[0], l[0]);
    split2(v.y, h[1], l[1]);
    split2(v.z, h[2], l[2]);
    split2(v.w, h[3], l[3]);
    uint2 u;
    u.x = pack2(h[0], h[1]); u.y = pack2(h[2], h[3]);
    *(uint2*)(out + idx) = u;
    u.x = pack2(l[0], l[1]); u.y = pack2(l[2], l[3]);
    *(uint2*)(out + ACT_PLANE + idx) = u;
}

// ---------------------------------------------------------------------------
// mlp6: ALL 6 layers in one kernel. 64 CTAs x 256 thr; CTA owns 16 m-rows,
// computes all 256 cols per layer; activations stay in smem.
// Weights stream via 3-slot TMA pipeline (24 stages of 64KB).
// ---------------------------------------------------------------------------
__global__ __launch_bounds__(256) void mlp6_kernel(
    const __grid_constant__ CUtensorMap tmW,
    const __half* __restrict__ actIn,
    const float* __restrict__ b0, const float* __restrict__ b1,
    const float* __restrict__ b2, const float* __restrict__ b3,
    const float* __restrict__ b4, const float* __restrict__ bp)
{
    extern __shared__ char smem[];
    const uint32_t sbase = cvta_smem(smem);
    const uint32_t MB = sbase + SM_MBAR;

    const int t    = threadIdx.x;
    const int lane = t & 31;
    const int wid  = t >> 5;
    const int m0   = blockIdx.x * 16;

    if (t == 0) {
        mbar_init(MB, 1);
        mbar_init(MB + 8, 1);
        mbar_init(MB + 16, 1);
    }
#pragma unroll
    for (int i = 0; i < 4; i++) {
        int id = i * 256 + t;
        int s = id >> 9;
        int r = (id >> 5) & 15;
        int c = id & 31;
        uint4 v = *(const uint4*)(actIn + (size_t)s * ACT_PLANE + (m0 + r) * 256 + c * 8);
        *(uint4*)(smem + SM_ACT0 + s * 8192 + r * 512 + swz(c, r & 7) * 16) = v;
    }
    __syncthreads();
    if (t == 0) {
        // prefetch stages 0,1,2 into slots 0,1,2
#pragma unroll
        for (int g = 0; g < 3; g++) {
            mbar_expect_tx(MB + g * 8, SLOT_BYTES);
            tma3d(sbase + g * SLOT_BYTES, &tmW, (g & 3) * 64, 0, (g >> 2) * 2,
                  MB + g * 8);
        }
    }

    const uint32_t rowA = lane & 15;
    const uint32_t ahi  = lane >> 4;
    const uint32_t axr  = rowA & 7;
    const uint32_t nloc0 = wid * 32 + ((lane >> 4) << 3) + (lane & 7);
    const uint32_t bhi  = (lane >> 3) & 1;
    const uint32_t bxr0 = nloc0 & 7;
    const uint32_t bxr1 = (nloc0 + 16) & 7;
    const int crow  = lane >> 2;
    const int ccol2 = (lane & 3) * 2;

    uint32_t par[3] = {0, 0, 0};
    int slot = 0;

#pragma unroll 1
    for (int L = 0; L < 6; L++) {
        const uint32_t actCur = sbase + ((L & 1) ? SM_ACT1 : SM_ACT0);
        float D0[4][4] = {}, D1[4][4] = {};

#pragma unroll
        for (int st = 0; st < 4; st++) {
            const int g = L * 4 + st;
            const uint32_t slotB = sbase + slot * SLOT_BYTES;
            mbar_wait(MB + slot * 8, par[slot]);
            par[slot] ^= 1;

#pragma unroll
            for (int kk = 0; kk < 4; kk++) {
                const uint32_t cA = swz(st * 8 + (kk << 1) + ahi, axr) << 4;
                uint32_t Ah[4], Al[4];
                ldsm4(Ah, actCur + rowA * 512 + cA);
                ldsm4(Al, actCur + 8192 + rowA * 512 + cA);
                const uint32_t cB0 = swz((kk << 1) + bhi, bxr0) << 4;
                const uint32_t cB1 = swz((kk << 1) + bhi, bxr1) << 4;
                uint32_t Bh[2][4], Bl[2][4];
                ldsm4(Bh[0], slotB + nloc0 * 128 + cB0);
                ldsm4(Bh[1], slotB + (nloc0 + 16) * 128 + cB1);
                ldsm4(Bl[0], slotB + 32768 + nloc0 * 128 + cB0);
                ldsm4(Bl[1], slotB + 32768 + (nloc0 + 16) * 128 + cB1);
#pragma unroll
                for (int ni = 0; ni < 4; ni++) {
                    const uint32_t* bh = &Bh[ni >> 1][(ni & 1) * 2];
                    const uint32_t* bl = &Bl[ni >> 1][(ni & 1) * 2];
                    mma16816(D0[ni], Ah, bh);
                    mma16816(D1[ni], Ah, bl);
                    mma16816(D1[ni], Al, bh);
                }
            }
            __syncthreads();   // slot fully consumed by all warps
            if (g + 3 < 24 && t == 0) {
                const int ng = g + 3;
                uint32_t mb = MB + slot * 8;
                mbar_expect_tx(mb, SLOT_BYTES);
                tma3d(sbase + slot * SLOT_BYTES, &tmW,
                      (ng & 3) * 64, 0, (ng >> 2) * 2, mb);
            }
            slot = (slot == 2) ? 0 : slot + 1;
        }

        const float* bias = (L == 0) ? b0 : (L == 1) ? b1 : (L == 2) ? b2
                          : (L == 3) ? b3 : (L == 4) ? b4 : bp;
        if (L < 5) {
            const uint32_t actNxt = sbase + ((L & 1) ? SM_ACT0 : SM_ACT1);
#pragma unroll
            for (int ni = 0; ni < 4; ni++) {
                int n = wid * 32 + ni * 8 + ccol2;
                float b0v = __ldg(&bias[n]);
                float b1v = __ldg(&bias[n + 1]);
                const uint32_t cN = n >> 3;
                const uint32_t intra = (n & 7) * 2;
#pragma unroll
                for (int hh = 0; hh < 2; hh++) {
                    float d0 = fmaf(D1[ni][hh * 2],     SC_L, D0[ni][hh * 2]);
                    float d1 = fmaf(D1[ni][hh * 2 + 1], SC_L, D0[ni][hh * 2 + 1]);
                    float y0 = fmaxf(d0 + b0v, 0.0f);
                    float y1 = fmaxf(d1 + b1v, 0.0f);
                    __half h0, l0, h1, l1;
                    split2(y0, h0, l0);
                    split2(y1, h1, l1);
                    const int m = crow + hh * 8;
                    uint32_t off = m * 512 + swz(cN, m & 7) * 16 + intra;
                    *(uint32_t*)((char*)smem + (actNxt - sbase) + off) = pack2(h0, h1);
                    *(uint32_t*)((char*)smem + (actNxt - sbase) + 8192 + off) = pack2(l0, l1);
                }
            }
            __syncthreads();
        } else {
#pragma unroll
            for (int ni = 0; ni < 4; ni++) {
                int n = wid * 32 + ni * 8 + ccol2;
                float b0v = __ldg(&bias[n]);
                float b1v = __ldg(&bias[n + 1]);
#pragma unroll
                for (int hh = 0; hh < 2; hh++) {
                    float d0 = fmaf(D1[ni][hh * 2],     SC_L, D0[ni][hh * 2]);
                    float d1 = fmaf(D1[ni][hh * 2 + 1], SC_L, D0[ni][hh * 2 + 1]);
                    const int m = m0 + crow + hh * 8;
                    float2 v;
                    v.x = d0 + b0v + 0.5f;
                    v.y = d1 + b1v + 0.5f;
                    *(float2*)(g_mu + m * 256 + n) = v;
                }
            }
        }
    }
}

// ---------------------------------------------------------------------------
// Fused tail: one CTA per batch row b; thread = (n, s), tid = 2n + s.
// Packed f32x2 m-loop with 4 independent accumulators.
// ---------------------------------------------------------------------------
__global__ __launch_bounds__(256) void tail_kernel(
    const float* __restrict__ realPoints,
    const float* __restrict__ predMu,
    const float* __restrict__ predScale,
    const float* __restrict__ eps,
    float* __restrict__ out)
{
    const int b = blockIdx.x;
    __shared__ float mu_s[256];                  // interleaved (n,k), for per-n use
    __shared__ __align__(16) float pkArr[256];   // {nm0_2p, nm0_2p+1, nm1_2p, nm1_2p+1}
    __shared__ __align__(16) float acArr[256];   // {am2_2p, am2_2p+1, cm2_2p, cm2_2p+1}
    __shared__ float sc[7];

    const int tid = threadIdx.x;
    mu_s[tid] = g_mu[b * 256 + tid];
    if (tid < 64) {
        const float* mb = g_mu + b * 256 + tid * 4;
        float4 v = *(const float4*)mb;
        ((float4*)pkArr)[tid] = make_float4(-v.x, -v.z, -v.y, -v.w);
        float devA = 0.001f + (float)(2 * tid)     * (0.009f / 127.0f);
        float devB = 0.001f + (float)(2 * tid + 1) * (0.009f / 127.0f);
        ((float4*)acArr)[tid] = make_float4(
            (-0.5f / (devA * devA)) * LOG2E_F,
            (-0.5f / (devB * devB)) * LOG2E_F,
            (-2.0f * logf(devA) - LOG2PI_F) * LOG2E_F,
            (-2.0f * logf(devB) - LOG2PI_F) * LOG2E_F);
    }
    if (tid == 0) {
        sc[0] = realPoints[b * 2];
        sc[1] = realPoints[b * 2 + 1];
        sc[2] = predMu[b * 2];
        sc[3] = predMu[b * 2 + 1];
        float p0 = predScale[b * 2], p1 = predScale[b * 2 + 1];
        sc[4] = 1.0f / p0;
        sc[5] = 1.0f / p1;
        sc[6] = logf(p0) + logf(p1);
    }
    __syncthreads();

    const int n = tid >> 1;
    const int s = tid & 1;

    const float mu0 = mu_s[2 * n];
    const float mu1 = mu_s[2 * n + 1];
    const float dev = 0.001f + (float)n * (0.009f / 127.0f);

    const int eoff = s * (BSZ * NPTS * 2) + (b * NPTS + n) * 2;
    const float e0 = eps[eoff];
    const float e1 = eps[eoff + 1];
    const float s0 = fmaf(dev, e0, mu0);
    const float s1 = fmaf(dev, e1, mu1);

    {
        long so = ((long)(s * NPTS + n) * BSZ + b) * 2;
        out[OFF_SAMPLED + so]     = s0;
        out[OFF_SAMPLED + so + 1] = s1;
    }

    // lossB: packed f32x2 loop over 64 m-pairs, 4 independent accumulators
    const ulonglong2* pk2 = (const ulonglong2*)pkArr;
    const ulonglong2* ac2 = (const ulonglong2*)acArr;
    const u64 s0p = packf2(s0, s0);
    const u64 s1p = packf2(s1, s1);
    u64 sm0 = packf2(0.0f, 0.0f), sm1 = sm0, sm2 = sm0, sm3 = sm0;
#pragma unroll 8
    for (int p = 0; p < 64; p += 4) {
#pragma unroll
        for (int j = 0; j < 4; j++) {
            ulonglong2 nm = pk2[p + j];
            ulonglong2 ac = ac2[p + j];
            u64 d0 = add2(s0p, nm.x);
            u64 d1 = add2(s1p, nm.y);
            u64 ss = fma2(d1, d1, mul2(d0, d0));
            u64 ar = fma2(ss, ac.x, ac.y);
            float alo, ahi;
            unpackf2(ar, alo, ahi);
            u64 ev = packf2(ex2f(alo), ex2f(ahi));
            if (j == 0) sm0 = add2(sm0, ev);
            else if (j == 1) sm1 = add2(sm1, ev);
            else if (j == 2) sm2 = add2(sm2, ev);
            else sm3 = add2(sm3, ev);
        }
    }
    u64 sumP = add2(add2(sm0, sm1), add2(sm2, sm3));
    float sLo, sHi;
    unpackf2(sumP, sLo, sHi);
    float sumexp = sLo + sHi;

    // diag term (same IEEE ops as one f32x2 lane of the loop)
    const float am2n = acArr[(n >> 1) * 4 + (n & 1)];
    const float cm2n = acArr[(n >> 1) * 4 + 2 + (n & 1)];
    {
        float d0 = s0 + pkArr[(n >> 1) * 4 + (n & 1)];
        float d1 = s1 + pkArr[(n >> 1) * 4 + 2 + (n & 1)];
        float ssn = fmaf(d1, d1, d0 * d0);
        float en = ex2f(fmaf(ssn, am2n, cm2n));
        float lbv = 1.0f - en / sumexp;
        out[OFF_LOSSB + b * 256 + tid] = lbv * lbv;
    }

    float z0 = (s0 - sc[2]) * sc[4];
    float z1 = (s1 - sc[3]) * sc[5];
    float lp = fmaf(-0.5f, fmaf(z0, z0, z1 * z1), -sc[6] - LOG2PI_F);
    float gl  = 1.0f / (1.0f + __expf(-lp));
    float sgn = 1.0f / (1.0f + __expf(lp));
    float tA  = LOG1P_HALF - log1pf(sgn);
    tA *= tA;

    float gl_o = __shfl_xor_sync(0xffffffffu, gl, 1);
    float tA_o = __shfl_xor_sync(0xffffffffu, tA, 1);

    if (s == 0) {
        float glm   = 0.5f * (gl + gl_o);
        float lossA = 0.5f * (tA + tA_o);
        float dr0 = sc[0] - mu0;
        float dr1 = sc[1] - mu1;
        float ssr = fmaf(dr1, dr1, dr0 * dr0);
        float rl  = 1.0f / (1.0f + ex2f(-fmaf(ssr, am2n, cm2n)));
        out[OFF_REAL  + b * NPTS + n] = rl;
        out[OFF_LOSSA + b * NPTS + n] = lossA;
        out[OFF_GEN   + b * NPTS + n] = glm * (1.0f - rl);
    }
}

// ---------------------------------------------------------------------------
typedef CUresult (*encode_fn_t)(
    CUtensorMap*, CUtensorMapDataType, cuuint32_t, void*,
    const cuuint64_t*, const cuuint64_t*, const cuuint32_t*, const cuuint32_t*,
    CUtensorMapInterleave, CUtensorMapSwizzle, CUtensorMapL2promotion,
    CUtensorMapFloatOOBfill);

extern "C" void kernel_launch(void* const* d_in, const int* in_sizes, int n_in,
                              void* d_out, int out_size) {
    const float* latents    = (const float*)d_in[0];
    const float* realPoints = (const float*)d_in[1];
    const float* predMu     = (const float*)d_in[2];
    const float* predScale  = (const float*)d_in[3];
    const float* eps        = (const float*)d_in[4];
    const float* W[5]  = {(const float*)d_in[5],  (const float*)d_in[7],
                          (const float*)d_in[9],  (const float*)d_in[11],
                          (const float*)d_in[13]};
    const float* bb[5] = {(const float*)d_in[6],  (const float*)d_in[8],
                          (const float*)d_in[10], (const float*)d_in[12],
                          (const float*)d_in[14]};
    const float* bp = (const float*)d_in[16];
    float* out = (float*)d_out;

    __half *gA, *gW;
    cudaGetSymbolAddress((void**)&gA, g_Act);
    cudaGetSymbolAddress((void**)&gW, g_Wsplit);

    void* fptr = nullptr;
    cudaDriverEntryPointQueryResult qr;
    cudaGetDriverEntryPoint("cuTensorMapEncodeTiled", &fptr,
                            cudaEnableDefault, &qr);
    encode_fn_t enc = (encode_fn_t)fptr;
    CUtensorMap tmW;
    {
        cuuint64_t dims[3]    = {256, 256, 12};
        cuuint64_t strides[2] = {512, 131072};
        cuuint32_t box[3]     = {64, 256, 2};
        cuuint32_t es[3]      = {1, 1, 1};
        enc(&tmW, CU_TENSOR_MAP_DATA_TYPE_FLOAT16, 3, gW, dims, strides, box, es,
            CU_TENSOR_MAP_INTERLEAVE_NONE, CU_TENSOR_MAP_SWIZZLE_128B,
            CU_TENSOR_MAP_L2_PROMOTION_L2_128B, CU_TENSOR_MAP_FLOAT_OOB_FILL_NONE);
    }

    cudaFuncSetAttribute(mlp6_kernel,
                         cudaFuncAttributeMaxDynamicSharedMemorySize, SM_TOTAL);

    prep_weights<<<dim3(32, 6), 256>>>(W[0], W[1], W[2], W[3], W[4],
                                       (const float*)d_in[15]);
    prep_latents<<<256, 256>>>(latents, gA);

    mlp6_kernel<<<64, 256, SM_TOTAL>>>(tmW, gA, bb[0], bb[1], bb[2],
                                       bb[3], bb[4], bp);

    tail_kernel<<<BSZ, 256>>>(realPoints, predMu, predScale, eps, out);
}

// round 16
// speedup vs baseline: 1.0007x; 1.0007x over previous
#include <cuda_runtime.h>
#include <cuda.h>
#include <cuda_fp16.h>
#include <math.h>
#include <stdint.h>

// Problem constants
#define BSZ   1024
#define NPTS  128
#define LOG2PI_F 1.8378770664093453f
#define LOG2E_F  1.4426950408889634f
#define LOG1P_HALF 0.40546510810816438f

// Output layout offsets
#define OFF_SAMPLED 0
#define OFF_GEN     524288
#define OFF_REAL    655360
#define OFF_LOSSA   786432
#define OFF_LOSSB   917504

// 2-way split: a = h + l'*2^-11  (residual ~2^-22)
#define SC_L 4.8828125e-4f            // 2^-11

#define ACT_PLANE 262144              // halves per activation plane (1024*256)
#define W_LAYER   (2 * 256 * 256)     // halves per layer of split weights

// mlp6 smem: 2 W slots (64KB each) + 2 act buffers (16KB each) + 2 mbars
#define SLOT_BYTES 65536
#define SM_ACT0    131072
#define SM_ACT1    147456
#define SM_MBAR    163840
#define SM_TOTAL   163904

typedef unsigned long long u64;

// Scratch (128B aligned for TMA)
__device__ __align__(128) __half g_Act[2 * ACT_PLANE];   // split latents (2 planes)
__device__ __align__(128) __half g_Wsplit[6 * W_LAYER];  // [L][split][n][k]
__device__ float g_mu[BSZ * 256];

// ---------------------------------------------------------------------------
// helpers
// ---------------------------------------------------------------------------
__device__ __forceinline__ uint32_t cvta_smem(const void* p) {
    uint32_t a;
    asm("{ .reg .u64 t; cvta.to.shared.u64 t, %1; cvt.u32.u64 %0, t; }"
        : "=r"(a) : "l"(p));
    return a;
}
__device__ __forceinline__ void ldsm4(uint32_t* r, uint32_t addr) {
    asm volatile("ldmatrix.sync.aligned.m8n8.x4.shared.b16 {%0,%1,%2,%3}, [%4];"
                 : "=r"(r[0]), "=r"(r[1]), "=r"(r[2]), "=r"(r[3]) : "r"(addr));
}
__device__ __forceinline__ void mma16816(float* d, const uint32_t* a, const uint32_t* b) {
    asm("mma.sync.aligned.m16n8k16.row.col.f32.f16.f16.f32 "
        "{%0,%1,%2,%3}, {%4,%5,%6,%7}, {%8,%9}, {%0,%1,%2,%3};"
        : "+f"(d[0]), "+f"(d[1]), "+f"(d[2]), "+f"(d[3])
        : "r"(a[0]), "r"(a[1]), "r"(a[2]), "r"(a[3]), "r"(b[0]), "r"(b[1]));
}
__device__ __forceinline__ void mbar_init(uint32_t a, uint32_t cnt) {
    asm volatile("mbarrier.init.shared.b64 [%0], %1;" :: "r"(a), "r"(cnt) : "memory");
}
__device__ __forceinline__ void mbar_expect_tx(uint32_t a, uint32_t bytes) {
    asm volatile("mbarrier.arrive.expect_tx.shared.b64 _, [%0], %1;"
                 :: "r"(a), "r"(bytes) : "memory");
}
__device__ __forceinline__ void mbar_wait(uint32_t mbar, uint32_t par) {
    asm volatile(
        "{\n\t.reg .pred P1;\n\t"
        "WAIT_LOOP_%=:\n\t"
        "mbarrier.try_wait.parity.shared::cta.b64 P1, [%0], %1, 0x989680;\n\t"
        "@P1 bra.uni WAIT_DONE_%=;\n\t"
        "bra.uni WAIT_LOOP_%=;\n\t"
        "WAIT_DONE_%=:\n\t}"
        :: "r"(mbar), "r"(par) : "memory");
}
__device__ __forceinline__ void tma3d(uint32_t sdst, const CUtensorMap* tm,
                                      int x, int y, int z, uint32_t mbar) {
    asm volatile(
        "cp.async.bulk.tensor.3d.shared::cta.global.tile.mbarrier::complete_tx::bytes "
        "[%0], [%1, {%2, %3, %4}], [%5];"
        :: "r"(sdst), "l"(tm), "r"(x), "r"(y), "r"(z), "r"(mbar) : "memory");
}
__device__ __forceinline__ float ex2f(float x) {
    float y;
    asm("ex2.approx.f32 %0, %1;" : "=f"(y) : "f"(x));
    return y;
}
__device__ __forceinline__ void split2(float a, __half& h, __half& l) {
    h = __float2half_rn(a);
    float r1 = a - __half2float(h);
    l = __float2half_rn(r1 * 2048.0f);
}
__device__ __forceinline__ uint32_t pack2(__half a, __half b) {
    __half2 h = __halves2half2(a, b);
    return *(uint32_t*)&h;
}
__device__ __forceinline__ uint32_t swz(uint32_t c, uint32_t r) {
    return (c & 24u) | ((c ^ r) & 7u);
}
// packed f32x2 ops
__device__ __forceinline__ u64 packf2(float lo, float hi) {
    u64 r;
    asm("mov.b64 %0, {%1, %2};" : "=l"(r) : "f"(lo), "f"(hi));
    return r;
}
__device__ __forceinline__ void unpackf2(u64 v, float& lo, float& hi) {
    asm("mov.b64 {%0, %1}, %2;" : "=f"(lo), "=f"(hi) : "l"(v));
}
__device__ __forceinline__ u64 add2(u64 a, u64 b) {
    u64 r;
    asm("add.rn.f32x2 %0, %1, %2;" : "=l"(r) : "l"(a), "l"(b));
    return r;
}
__device__ __forceinline__ u64 mul2(u64 a, u64 b) {
    u64 r;
    asm("mul.rn.f32x2 %0, %1, %2;" : "=l"(r) : "l"(a), "l"(b));
    return r;
}
__device__ __forceinline__ u64 fma2(u64 a, u64 b, u64 c) {
    u64 r;
    asm("fma.rn.f32x2 %0, %1, %2, %3;" : "=l"(r) : "l"(a), "l"(b), "l"(c));
    return r;
}

// ---------------------------------------------------------------------------
// prep: g_Wsplit[L][s][n][k] fp16 2-split of W_L^T (L=5 is Wp reshaped)
// ---------------------------------------------------------------------------
__global__ __launch_bounds__(256) void prep_weights(
    const float* __restrict__ W0, const float* __restrict__ W1,
    const float* __restrict__ W2, const float* __restrict__ W3,
    const float* __restrict__ W4, const float* __restrict__ Wp)
{
    __shared__ float stage[256][9];
    const int L  = blockIdx.y;
    const int n0 = blockIdx.x * 8;
    const int t  = threadIdx.x;

    {
        const int k = t;
        if (L < 5) {
            const float* W = (L == 0) ? W0 : (L == 1) ? W1 : (L == 2) ? W2
                           : (L == 3) ? W3 : W4;
            float4 v0 = *(const float4*)&W[k * 256 + n0];
            float4 v1 = *(const float4*)&W[k * 256 + n0 + 4];
            stage[k][0] = v0.x; stage[k][1] = v0.y; stage[k][2] = v0.z; stage[k][3] = v0.w;
            stage[k][4] = v1.x; stage[k][5] = v1.y; stage[k][6] = v1.z; stage[k][7] = v1.w;
        } else {
#pragma unroll
            for (int j = 0; j < 8; j++) {
                int n = n0 + j;
                stage[k][j] = Wp[(n >> 1) * 512 + k * 2 + (n & 1)];
            }
        }
    }
    __syncthreads();
    {
        const int nl = t >> 5;
        const int k0 = (t & 31) * 8;
        __half h[8], l[8];
#pragma unroll
        for (int i = 0; i < 8; i++)
            split2(stage[k0 + i][nl], h[i], l[i]);
        const int n = n0 + nl;
        __half* base = g_Wsplit + (size_t)L * W_LAYER;
        uint4 v;
        v.x = pack2(h[0], h[1]); v.y = pack2(h[2], h[3]);
        v.z = pack2(h[4], h[5]); v.w = pack2(h[6], h[7]);
        *(uint4*)(base + (0 * 256 + n) * 256 + k0) = v;
        v.x = pack2(l[0], l[1]); v.y = pack2(l[2], l[3]);
        v.z = pack2(l[4], l[5]); v.w = pack2(l[6], l[7]);
        *(uint4*)(base + (1 * 256 + n) * 256 + k0) = v;
    }
}

// ---------------------------------------------------------------------------
// prep latents: fp32 [1024][256] -> 2 fp16 split planes
// ---------------------------------------------------------------------------
__global__ __launch_bounds__(256) void prep_latents(
    const float* __restrict__ L, __half* __restrict__ out)
{
    int idx = (blockIdx.x * 256 + threadIdx.x) * 4;
    float4 v = *(const float4*)(L + idx);
    __half h[4], l[4];
    split2(v.x, h[0], l[0]);
    split2(v.y, h[1], l[1]);
    split2(v.z, h[2], l[2]);
    split2(v.w, h[3], l[3]);
    uint2 u;
    u.x = pack2(h[0], h[1]); u.y = pack2(h[2], h[3]);
    *(uint2*)(out + idx) = u;
    u.x = pack2(l[0], l[1]); u.y = pack2(l[2], l[3]);
    *(uint2*)(out + ACT_PLANE + idx) = u;
}

// ---------------------------------------------------------------------------
// mlp6: ALL 6 layers in one kernel. 64 CTAs x 256 thr; CTA owns 16 m-rows,
// computes all 256 cols per layer; activations stay in smem.
// Weights stream via 2-slot TMA pipeline (24 stages of 64KB).  [R14 config]
// ---------------------------------------------------------------------------
__global__ __launch_bounds__(256) void mlp6_kernel(
    const __grid_constant__ CUtensorMap tmW,
    const __half* __restrict__ actIn,
    const float* __restrict__ b0, const float* __restrict__ b1,
    const float* __restrict__ b2, const float* __restrict__ b3,
    const float* __restrict__ b4, const float* __restrict__ bp)
{
    extern __shared__ char smem[];
    const uint32_t sbase = cvta_smem(smem);
    const uint32_t MB = sbase + SM_MBAR;

    const int t    = threadIdx.x;
    const int lane = t & 31;
    const int wid  = t >> 5;
    const int m0   = blockIdx.x * 16;

    if (t == 0) {
        mbar_init(MB, 1);
        mbar_init(MB + 8, 1);
    }
#pragma unroll
    for (int i = 0; i < 4; i++) {
        int id = i * 256 + t;
        int s = id >> 9;
        int r = (id >> 5) & 15;
        int c = id & 31;
        uint4 v = *(const uint4*)(actIn + (size_t)s * ACT_PLANE + (m0 + r) * 256 + c * 8);
        *(uint4*)(smem + SM_ACT0 + s * 8192 + r * 512 + swz(c, r & 7) * 16) = v;
    }
    __syncthreads();
    if (t == 0) {
        mbar_expect_tx(MB, SLOT_BYTES);
        tma3d(sbase, &tmW, 0, 0, 0, MB);
        mbar_expect_tx(MB + 8, SLOT_BYTES);
        tma3d(sbase + SLOT_BYTES, &tmW, 64, 0, 0, MB + 8);
    }

    const uint32_t rowA = lane & 15;
    const uint32_t ahi  = lane >> 4;
    const uint32_t axr  = rowA & 7;
    const uint32_t nloc0 = wid * 32 + ((lane >> 4) << 3) + (lane & 7);
    const uint32_t bhi  = (lane >> 3) & 1;
    const uint32_t bxr0 = nloc0 & 7;
    const uint32_t bxr1 = (nloc0 + 16) & 7;
    const int crow  = lane >> 2;
    const int ccol2 = (lane & 3) * 2;

    uint32_t par0 = 0, par1 = 0;

#pragma unroll 1
    for (int L = 0; L < 6; L++) {
        const uint32_t actCur = sbase + ((L & 1) ? SM_ACT1 : SM_ACT0);
        float D0[4][4] = {}, D1[4][4] = {};

#pragma unroll
        for (int st = 0; st < 4; st++) {
            const int g = L * 4 + st;
            const int slot = g & 1;
            const uint32_t slotB = sbase + slot * SLOT_BYTES;
            if (slot == 0) { mbar_wait(MB, par0);     par0 ^= 1; }
            else           { mbar_wait(MB + 8, par1); par1 ^= 1; }

#pragma unroll
            for (int kk = 0; kk < 4; kk++) {
                const uint32_t cA = swz(st * 8 + (kk << 1) + ahi, axr) << 4;
                uint32_t Ah[4], Al[4];
                ldsm4(Ah, actCur + rowA * 512 + cA);
                ldsm4(Al, actCur + 8192 + rowA * 512 + cA);
                const uint32_t cB0 = swz((kk << 1) + bhi, bxr0) << 4;
                const uint32_t cB1 = swz((kk << 1) + bhi, bxr1) << 4;
                uint32_t Bh[2][4], Bl[2][4];
                ldsm4(Bh[0], slotB + nloc0 * 128 + cB0);
                ldsm4(Bh[1], slotB + (nloc0 + 16) * 128 + cB1);
                ldsm4(Bl[0], slotB + 32768 + nloc0 * 128 + cB0);
                ldsm4(Bl[1], slotB + 32768 + (nloc0 + 16) * 128 + cB1);
#pragma unroll
                for (int ni = 0; ni < 4; ni++) {
                    const uint32_t* bh = &Bh[ni >> 1][(ni & 1) * 2];
                    const uint32_t* bl = &Bl[ni >> 1][(ni & 1) * 2];
                    mma16816(D0[ni], Ah, bh);
                    mma16816(D1[ni], Ah, bl);
                    mma16816(D1[ni], Al, bh);
                }
            }
            __syncthreads();
            if (g + 2 < 24 && t == 0) {
                const int ng = g + 2;
                uint32_t mb = MB + slot * 8;
                mbar_expect_tx(mb, SLOT_BYTES);
                tma3d(sbase + slot * SLOT_BYTES, &tmW,
                      (ng & 3) * 64, 0, (ng >> 2) * 2, mb);
            }
        }

        const float* bias = (L == 0) ? b0 : (L == 1) ? b1 : (L == 2) ? b2
                          : (L == 3) ? b3 : (L == 4) ? b4 : bp;
        if (L < 5) {
            const uint32_t actNxt = sbase + ((L & 1) ? SM_ACT0 : SM_ACT1);
#pragma unroll
            for (int ni = 0; ni < 4; ni++) {
                int n = wid * 32 + ni * 8 + ccol2;
                float b0v = __ldg(&bias[n]);
                float b1v = __ldg(&bias[n + 1]);
                const uint32_t cN = n >> 3;
                const uint32_t intra = (n & 7) * 2;
#pragma unroll
                for (int hh = 0; hh < 2; hh++) {
                    float d0 = fmaf(D1[ni][hh * 2],     SC_L, D0[ni][hh * 2]);
                    float d1 = fmaf(D1[ni][hh * 2 + 1], SC_L, D0[ni][hh * 2 + 1]);
                    float y0 = fmaxf(d0 + b0v, 0.0f);
                    float y1 = fmaxf(d1 + b1v, 0.0f);
                    __half h0, l0, h1, l1;
                    split2(y0, h0, l0);
                    split2(y1, h1, l1);
                    const int m = crow + hh * 8;
                    uint32_t off = m * 512 + swz(cN, m & 7) * 16 + intra;
                    *(uint32_t*)((char*)smem + (actNxt - sbase) + off) = pack2(h0, h1);
                    *(uint32_t*)((char*)smem + (actNxt - sbase) + 8192 + off) = pack2(l0, l1);
                }
            }
            __syncthreads();
        } else {
#pragma unroll
            for (int ni = 0; ni < 4; ni++) {
                int n = wid * 32 + ni * 8 + ccol2;
                float b0v = __ldg(&bias[n]);
                float b1v = __ldg(&bias[n + 1]);
#pragma unroll
                for (int hh = 0; hh < 2; hh++) {
                    float d0 = fmaf(D1[ni][hh * 2],     SC_L, D0[ni][hh * 2]);
                    float d1 = fmaf(D1[ni][hh * 2 + 1], SC_L, D0[ni][hh * 2 + 1]);
                    const int m = m0 + crow + hh * 8;
                    float2 v;
                    v.x = d0 + b0v + 0.5f;
                    v.y = d1 + b1v + 0.5f;
                    *(float2*)(g_mu + m * 256 + n) = v;
                }
            }
        }
    }
}

// ---------------------------------------------------------------------------
// Fused tail: one CTA per TWO batch rows (b, b+512); thread = (n, s).
// Two independent packed-f32x2 m-loops interleaved for ILP.
// ---------------------------------------------------------------------------
__global__ __launch_bounds__(256) void tail_kernel(
    const float* __restrict__ realPoints,
    const float* __restrict__ predMu,
    const float* __restrict__ predScale,
    const float* __restrict__ eps,
    float* __restrict__ out)
{
    const int bA = blockIdx.x;
    const int bB = blockIdx.x + 512;
    __shared__ __align__(16) float pkA[256];     // -mu of bA, packed pairs
    __shared__ __align__(16) float pkB[256];     // -mu of bB
    __shared__ __align__(16) float acArr[256];   // {am2,am2,cm2,cm2} pairs
    __shared__ float scA[8], scB[8];

    const int tid = threadIdx.x;
    if (tid < 64) {
        float4 v = *(const float4*)(g_mu + bA * 256 + tid * 4);
        ((float4*)pkA)[tid] = make_float4(-v.x, -v.z, -v.y, -v.w);
        v = *(const float4*)(g_mu + bB * 256 + tid * 4);
        ((float4*)pkB)[tid] = make_float4(-v.x, -v.z, -v.y, -v.w);
        float devA_ = 0.001f + (float)(2 * tid)     * (0.009f / 127.0f);
        float devB_ = 0.001f + (float)(2 * tid + 1) * (0.009f / 127.0f);
        ((float4*)acArr)[tid] = make_float4(
            (-0.5f / (devA_ * devA_)) * LOG2E_F,
            (-0.5f / (devB_ * devB_)) * LOG2E_F,
            (-2.0f * logf(devA_) - LOG2PI_F) * LOG2E_F,
            (-2.0f * logf(devB_) - LOG2PI_F) * LOG2E_F);
    }
    if (tid < 2) {
        int bb = tid ? bB : bA;
        float* sc = tid ? scB : scA;
        sc[0] = realPoints[bb * 2];
        sc[1] = realPoints[bb * 2 + 1];
        sc[2] = predMu[bb * 2];
        sc[3] = predMu[bb * 2 + 1];
        float p0 = predScale[bb * 2], p1 = predScale[bb * 2 + 1];
        sc[4] = 1.0f / p0;
        sc[5] = 1.0f / p1;
        sc[6] = logf(p0) + logf(p1);
    }
    __syncthreads();

    const int n = tid >> 1;
    const int s = tid & 1;
    const float dev = 0.001f + (float)n * (0.009f / 127.0f);
    const int pkIdx0 = (n >> 1) * 4 + (n & 1);
    const int pkIdx1 = pkIdx0 + 2;

    float mu0[2], mu1[2], s0v[2], s1v[2];
    const int bs[2] = {bA, bB};
    const float* pk[2] = {pkA, pkB};
#pragma unroll
    for (int j = 0; j < 2; j++) {
        mu0[j] = -pk[j][pkIdx0];
        mu1[j] = -pk[j][pkIdx1];
        const int eoff = s * (BSZ * NPTS * 2) + (bs[j] * NPTS + n) * 2;
        s0v[j] = fmaf(dev, eps[eoff],     mu0[j]);
        s1v[j] = fmaf(dev, eps[eoff + 1], mu1[j]);
        long so = ((long)(s * NPTS + n) * BSZ + bs[j]) * 2;
        out[OFF_SAMPLED + so]     = s0v[j];
        out[OFF_SAMPLED + so + 1] = s1v[j];
    }

    // interleaved packed m-loops for bA and bB
    const ulonglong2* pkA2 = (const ulonglong2*)pkA;
    const ulonglong2* pkB2 = (const ulonglong2*)pkB;
    const ulonglong2* ac2  = (const ulonglong2*)acArr;
    const u64 s0A = packf2(s0v[0], s0v[0]);
    const u64 s1A = packf2(s1v[0], s1v[0]);
    const u64 s0B = packf2(s0v[1], s0v[1]);
    const u64 s1B = packf2(s1v[1], s1v[1]);
    u64 smA = packf2(0.0f, 0.0f), smB = smA;
#pragma unroll 4
    for (int p = 0; p < 64; p++) {
        ulonglong2 ac = ac2[p];
        {
            ulonglong2 nm = pkA2[p];
            u64 d0 = add2(s0A, nm.x);
            u64 d1 = add2(s1A, nm.y);
            u64 ss = fma2(d1, d1, mul2(d0, d0));
            u64 ar = fma2(ss, ac.x, ac.y);
            float alo, ahi;
            unpackf2(ar, alo, ahi);
            smA = add2(smA, packf2(ex2f(alo), ex2f(ahi)));
        }
        {
            ulonglong2 nm = pkB2[p];
            u64 d0 = add2(s0B, nm.x);
            u64 d1 = add2(s1B, nm.y);
            u64 ss = fma2(d1, d1, mul2(d0, d0));
            u64 ar = fma2(ss, ac.x, ac.y);
            float alo, ahi;
            unpackf2(ar, alo, ahi);
            smB = add2(smB, packf2(ex2f(alo), ex2f(ahi)));
        }
    }
    float sumexp[2];
    {
        float lo, hi;
        unpackf2(smA, lo, hi);
        sumexp[0] = lo + hi;
        unpackf2(smB, lo, hi);
        sumexp[1] = lo + hi;
    }

    const float am2n = acArr[pkIdx0];
    const float cm2n = acArr[pkIdx1];
#pragma unroll
    for (int j = 0; j < 2; j++) {
        // diag term (same IEEE ops as one f32x2 lane of the loop)
        {
            float d0 = s0v[j] + pk[j][pkIdx0];
            float d1 = s1v[j] + pk[j][pkIdx1];
            float ssn = fmaf(d1, d1, d0 * d0);
            float en = ex2f(fmaf(ssn, am2n, cm2n));
            float lbv = 1.0f - en / sumexp[j];
            out[OFF_LOSSB + bs[j] * 256 + tid] = lbv * lbv;
        }
        const float* sc = j ? scB : scA;
        float z0 = (s0v[j] - sc[2]) * sc[4];
        float z1 = (s1v[j] - sc[3]) * sc[5];
        float lp = fmaf(-0.5f, fmaf(z0, z0, z1 * z1), -sc[6] - LOG2PI_F);
        float gl  = 1.0f / (1.0f + __expf(-lp));
        float sgn = 1.0f / (1.0f + __expf(lp));
        float tA  = LOG1P_HALF - log1pf(sgn);
        tA *= tA;

        float gl_o = __shfl_xor_sync(0xffffffffu, gl, 1);
        float tA_o = __shfl_xor_sync(0xffffffffu, tA, 1);

        if (s == 0) {
            float glm   = 0.5f * (gl + gl_o);
            float lossA = 0.5f * (tA + tA_o);
            float dr0 = sc[0] - mu0[j];
            float dr1 = sc[1] - mu1[j];
            float ssr = fmaf(dr1, dr1, dr0 * dr0);
            float rl  = 1.0f / (1.0f + ex2f(-fmaf(ssr, am2n, cm2n)));
            out[OFF_REAL  + bs[j] * NPTS + n] = rl;
            out[OFF_LOSSA + bs[j] * NPTS + n] = lossA;
            out[OFF_GEN   + bs[j] * NPTS + n] = glm * (1.0f - rl);
        }
    }
}

// ---------------------------------------------------------------------------
typedef CUresult (*encode_fn_t)(
    CUtensorMap*, CUtensorMapDataType, cuuint32_t, void*,
    const cuuint64_t*, const cuuint64_t*, const cuuint32_t*, const cuuint32_t*,
    CUtensorMapInterleave, CUtensorMapSwizzle, CUtensorMapL2promotion,
    CUtensorMapFloatOOBfill);

extern "C" void kernel_launch(void* const* d_in, const int* in_sizes, int n_in,
                              void* d_out, int out_size) {
    const float* latents    = (const float*)d_in[0];
    const float* realPoints = (const float*)d_in[1];
    const float* predMu     = (const float*)d_in[2];
    const float* predScale  = (const float*)d_in[3];
    const float* eps        = (const float*)d_in[4];
    const float* W[5]  = {(const float*)d_in[5],  (const float*)d_in[7],
                          (const float*)d_in[9],  (const float*)d_in[11],
                          (const float*)d_in[13]};
    const float* bb[5] = {(const float*)d_in[6],  (const float*)d_in[8],
                          (const float*)d_in[10], (const float*)d_in[12],
                          (const float*)d_in[14]};
    const float* bp = (const float*)d_in[16];
    float* out = (float*)d_out;

    __half *gA, *gW;
    cudaGetSymbolAddress((void**)&gA, g_Act);
    cudaGetSymbolAddress((void**)&gW, g_Wsplit);

    void* fptr = nullptr;
    cudaDriverEntryPointQueryResult qr;
    cudaGetDriverEntryPoint("cuTensorMapEncodeTiled", &fptr,
                            cudaEnableDefault, &qr);
    encode_fn_t enc = (encode_fn_t)fptr;
    CUtensorMap tmW;
    {
        cuuint64_t dims[3]    = {256, 256, 12};
        cuuint64_t strides[2] = {512, 131072};
        cuuint32_t box[3]     = {64, 256, 2};
        cuuint32_t es[3]      = {1, 1, 1};
        enc(&tmW, CU_TENSOR_MAP_DATA_TYPE_FLOAT16, 3, gW, dims, strides, box, es,
            CU_TENSOR_MAP_INTERLEAVE_NONE, CU_TENSOR_MAP_SWIZZLE_128B,
            CU_TENSOR_MAP_L2_PROMOTION_L2_128B, CU_TENSOR_MAP_FLOAT_OOB_FILL_NONE);
    }

    cudaFuncSetAttribute(mlp6_kernel,
                         cudaFuncAttributeMaxDynamicSharedMemorySize, SM_TOTAL);

    prep_weights<<<dim3(32, 6), 256>>>(W[0], W[1], W[2], W[3], W[4],
                                       (const float*)d_in[15]);
    prep_latents<<<256, 256>>>(latents, gA);

    mlp6_kernel<<<64, 256, SM_TOTAL>>>(tmW, gA, bb[0], bb[1], bb[2],
                                       bb[3], bb[4], bp);

    tail_kernel<<<512, 256>>>(realPoints, predMu, predScale, eps, out);
}

// round 17
// speedup vs baseline: 1.0534x; 1.0527x over previous
#include <cuda_runtime.h>
#include <cuda.h>
#include <cuda_fp16.h>
#include <math.h>
#include <stdint.h>

// Problem constants
#define BSZ   1024
#define NPTS  128
#define LOG2PI_F 1.8378770664093453f
#define LOG2E_F  1.4426950408889634f
#define LOG1P_HALF 0.40546510810816438f

// Output layout offsets
#define OFF_SAMPLED 0
#define OFF_GEN     524288
#define OFF_REAL    655360
#define OFF_LOSSA   786432
#define OFF_LOSSB   917504

// 2-way split: a = h + l'*2^-11  (residual ~2^-22)
#define SC_L 4.8828125e-4f            // 2^-11

#define ACT_PLANE 262144              // halves per activation plane (1024*256)
#define W_LAYER   (2 * 256 * 256)     // halves per layer of split weights

// mlp6 smem: 2 W slots (64KB each) + 2 act buffers (16KB each) + 2 mbars
#define SLOT_BYTES 65536
#define SM_ACT0    131072
#define SM_ACT1    147456
#define SM_MBAR    163840
#define SM_TOTAL   163904

typedef unsigned long long u64;

// Scratch (128B aligned for TMA)
__device__ __align__(128) __half g_Act[2 * ACT_PLANE];   // split latents (2 planes)
__device__ __align__(128) __half g_Wsplit[6 * W_LAYER];  // [L][split][n][k]
__device__ float g_mu[BSZ * 256];

// ---------------------------------------------------------------------------
// helpers
// ---------------------------------------------------------------------------
__device__ __forceinline__ uint32_t cvta_smem(const void* p) {
    uint32_t a;
    asm("{ .reg .u64 t; cvta.to.shared.u64 t, %1; cvt.u32.u64 %0, t; }"
        : "=r"(a) : "l"(p));
    return a;
}
__device__ __forceinline__ void ldsm4(uint32_t* r, uint32_t addr) {
    asm volatile("ldmatrix.sync.aligned.m8n8.x4.shared.b16 {%0,%1,%2,%3}, [%4];"
                 : "=r"(r[0]), "=r"(r[1]), "=r"(r[2]), "=r"(r[3]) : "r"(addr));
}
__device__ __forceinline__ void mma16816(float* d, const uint32_t* a, const uint32_t* b) {
    asm("mma.sync.aligned.m16n8k16.row.col.f32.f16.f16.f32 "
        "{%0,%1,%2,%3}, {%4,%5,%6,%7}, {%8,%9}, {%0,%1,%2,%3};"
        : "+f"(d[0]), "+f"(d[1]), "+f"(d[2]), "+f"(d[3])
        : "r"(a[0]), "r"(a[1]), "r"(a[2]), "r"(a[3]), "r"(b[0]), "r"(b[1]));
}
__device__ __forceinline__ void mbar_init(uint32_t a, uint32_t cnt) {
    asm volatile("mbarrier.init.shared.b64 [%0], %1;" :: "r"(a), "r"(cnt) : "memory");
}
__device__ __forceinline__ void mbar_expect_tx(uint32_t a, uint32_t bytes) {
    asm volatile("mbarrier.arrive.expect_tx.shared.b64 _, [%0], %1;"
                 :: "r"(a), "r"(bytes) : "memory");
}
__device__ __forceinline__ void mbar_wait(uint32_t mbar, uint32_t par) {
    asm volatile(
        "{\n\t.reg .pred P1;\n\t"
        "WAIT_LOOP_%=:\n\t"
        "mbarrier.try_wait.parity.shared::cta.b64 P1, [%0], %1, 0x989680;\n\t"
        "@P1 bra.uni WAIT_DONE_%=;\n\t"
        "bra.uni WAIT_LOOP_%=;\n\t"
        "WAIT_DONE_%=:\n\t}"
        :: "r"(mbar), "r"(par) : "memory");
}
__device__ __forceinline__ void tma3d(uint32_t sdst, const CUtensorMap* tm,
                                      int x, int y, int z, uint32_t mbar) {
    asm volatile(
        "cp.async.bulk.tensor.3d.shared::cta.global.tile.mbarrier::complete_tx::bytes "
        "[%0], [%1, {%2, %3, %4}], [%5];"
        :: "r"(sdst), "l"(tm), "r"(x), "r"(y), "r"(z), "r"(mbar) : "memory");
}
__device__ __forceinline__ float ex2f(float x) {
    float y;
    asm("ex2.approx.f32 %0, %1;" : "=f"(y) : "f"(x));
    return y;
}
__device__ __forceinline__ void split2(float a, __half& h, __half& l) {
    h = __float2half_rn(a);
    float r1 = a - __half2float(h);
    l = __float2half_rn(r1 * 2048.0f);
}
__device__ __forceinline__ uint32_t pack2(__half a, __half b) {
    __half2 h = __halves2half2(a, b);
    return *(uint32_t*)&h;
}
__device__ __forceinline__ uint32_t swz(uint32_t c, uint32_t r) {
    return (c & 24u) | ((c ^ r) & 7u);
}
// packed f32x2 ops
__device__ __forceinline__ u64 packf2(float lo, float hi) {
    u64 r;
    asm("mov.b64 %0, {%1, %2};" : "=l"(r) : "f"(lo), "f"(hi));
    return r;
}
__device__ __forceinline__ void unpackf2(u64 v, float& lo, float& hi) {
    asm("mov.b64 {%0, %1}, %2;" : "=f"(lo), "=f"(hi) : "l"(v));
}
__device__ __forceinline__ u64 add2(u64 a, u64 b) {
    u64 r;
    asm("add.rn.f32x2 %0, %1, %2;" : "=l"(r) : "l"(a), "l"(b));
    return r;
}
__device__ __forceinline__ u64 mul2(u64 a, u64 b) {
    u64 r;
    asm("mul.rn.f32x2 %0, %1, %2;" : "=l"(r) : "l"(a), "l"(b));
    return r;
}
__device__ __forceinline__ u64 fma2(u64 a, u64 b, u64 c) {
    u64 r;
    asm("fma.rn.f32x2 %0, %1, %2, %3;" : "=l"(r) : "l"(a), "l"(b), "l"(c));
    return r;
}

// ---------------------------------------------------------------------------
// merged prep: blocks 0..191 build g_Wsplit; blocks 192..447 split latents.
// ---------------------------------------------------------------------------
__global__ __launch_bounds__(256) void prep_kernel(
    const float* __restrict__ W0, const float* __restrict__ W1,
    const float* __restrict__ W2, const float* __restrict__ W3,
    const float* __restrict__ W4, const float* __restrict__ Wp,
    const float* __restrict__ latents, __half* __restrict__ actOut)
{
    const int bx = blockIdx.x;
    const int t  = threadIdx.x;

    if (bx >= 192) {
        // latents: fp32 [1024][256] -> 2 fp16 split planes
        int idx = ((bx - 192) * 256 + t) * 4;
        float4 v = *(const float4*)(latents + idx);
        __half h[4], l[4];
        split2(v.x, h[0], l[0]);
        split2(v.y, h[1], l[1]);
        split2(v.z, h[2], l[2]);
        split2(v.w, h[3], l[3]);
        uint2 u;
        u.x = pack2(h[0], h[1]); u.y = pack2(h[2], h[3]);
        *(uint2*)(actOut + idx) = u;
        u.x = pack2(l[0], l[1]); u.y = pack2(l[2], l[3]);
        *(uint2*)(actOut + ACT_PLANE + idx) = u;
        return;
    }

    // weights: g_Wsplit[L][s][n][k] fp16 2-split of W_L^T (L=5 is Wp reshaped)
    __shared__ float stage[256][9];
    const int L  = bx >> 5;
    const int n0 = (bx & 31) * 8;

    {
        const int k = t;
        if (L < 5) {
            const float* W = (L == 0) ? W0 : (L == 1) ? W1 : (L == 2) ? W2
                           : (L == 3) ? W3 : W4;
            float4 v0 = *(const float4*)&W[k * 256 + n0];
            float4 v1 = *(const float4*)&W[k * 256 + n0 + 4];
            stage[k][0] = v0.x; stage[k][1] = v0.y; stage[k][2] = v0.z; stage[k][3] = v0.w;
            stage[k][4] = v1.x; stage[k][5] = v1.y; stage[k][6] = v1.z; stage[k][7] = v1.w;
        } else {
#pragma unroll
            for (int j = 0; j < 8; j++) {
                int n = n0 + j;
                stage[k][j] = Wp[(n >> 1) * 512 + k * 2 + (n & 1)];
            }
        }
    }
    __syncthreads();
    {
        const int nl = t >> 5;
        const int k0 = (t & 31) * 8;
        __half h[8], l[8];
#pragma unroll
        for (int i = 0; i < 8; i++)
            split2(stage[k0 + i][nl], h[i], l[i]);
        const int n = n0 + nl;
        __half* base = g_Wsplit + (size_t)L * W_LAYER;
        uint4 v;
        v.x = pack2(h[0], h[1]); v.y = pack2(h[2], h[3]);
        v.z = pack2(h[4], h[5]); v.w = pack2(h[6], h[7]);
        *(uint4*)(base + (0 * 256 + n) * 256 + k0) = v;
        v.x = pack2(l[0], l[1]); v.y = pack2(l[2], l[3]);
        v.z = pack2(l[4], l[5]); v.w = pack2(l[6], l[7]);
        *(uint4*)(base + (1 * 256 + n) * 256 + k0) = v;
    }
}

// ---------------------------------------------------------------------------
// mlp6: ALL 6 layers in one kernel. 64 CTAs x 256 thr; CTA owns 16 m-rows,
// computes all 256 cols per layer; activations stay in smem.
// Weights stream via 2-slot TMA pipeline (24 stages of 64KB).  [R14 config]
// ---------------------------------------------------------------------------
__global__ __launch_bounds__(256) void mlp6_kernel(
    const __grid_constant__ CUtensorMap tmW,
    const __half* __restrict__ actIn,
    const float* __restrict__ b0, const float* __restrict__ b1,
    const float* __restrict__ b2, const float* __restrict__ b3,
    const float* __restrict__ b4, const float* __restrict__ bp)
{
    extern __shared__ char smem[];
    const uint32_t sbase = cvta_smem(smem);
    const uint32_t MB = sbase + SM_MBAR;

    const int t    = threadIdx.x;
    const int lane = t & 31;
    const int wid  = t >> 5;
    const int m0   = blockIdx.x * 16;

    if (t == 0) {
        mbar_init(MB, 1);
        mbar_init(MB + 8, 1);
    }
#pragma unroll
    for (int i = 0; i < 4; i++) {
        int id = i * 256 + t;
        int s = id >> 9;
        int r = (id >> 5) & 15;
        int c = id & 31;
        uint4 v = *(const uint4*)(actIn + (size_t)s * ACT_PLANE + (m0 + r) * 256 + c * 8);
        *(uint4*)(smem + SM_ACT0 + s * 8192 + r * 512 + swz(c, r & 7) * 16) = v;
    }
    __syncthreads();
    if (t == 0) {
        mbar_expect_tx(MB, SLOT_BYTES);
        tma3d(sbase, &tmW, 0, 0, 0, MB);
        mbar_expect_tx(MB + 8, SLOT_BYTES);
        tma3d(sbase + SLOT_BYTES, &tmW, 64, 0, 0, MB + 8);
    }

    const uint32_t rowA = lane & 15;
    const uint32_t ahi  = lane >> 4;
    const uint32_t axr  = rowA & 7;
    const uint32_t nloc0 = wid * 32 + ((lane >> 4) << 3) + (lane & 7);
    const uint32_t bhi  = (lane >> 3) & 1;
    const uint32_t bxr0 = nloc0 & 7;
    const uint32_t bxr1 = (nloc0 + 16) & 7;
    const int crow  = lane >> 2;
    const int ccol2 = (lane & 3) * 2;

    uint32_t par0 = 0, par1 = 0;

#pragma unroll 1
    for (int L = 0; L < 6; L++) {
        const uint32_t actCur = sbase + ((L & 1) ? SM_ACT1 : SM_ACT0);
        float D0[4][4] = {}, D1[4][4] = {};

#pragma unroll
        for (int st = 0; st < 4; st++) {
            const int g = L * 4 + st;
            const int slot = g & 1;
            const uint32_t slotB = sbase + slot * SLOT_BYTES;
            if (slot == 0) { mbar_wait(MB, par0);     par0 ^= 1; }
            else           { mbar_wait(MB + 8, par1); par1 ^= 1; }

#pragma unroll
            for (int kk = 0; kk < 4; kk++) {
                const uint32_t cA = swz(st * 8 + (kk << 1) + ahi, axr) << 4;
                uint32_t Ah[4], Al[4];
                ldsm4(Ah, actCur + rowA * 512 + cA);
                ldsm4(Al, actCur + 8192 + rowA * 512 + cA);
                const uint32_t cB0 = swz((kk << 1) + bhi, bxr0) << 4;
                const uint32_t cB1 = swz((kk << 1) + bhi, bxr1) << 4;
                uint32_t Bh[2][4], Bl[2][4];
                ldsm4(Bh[0], slotB + nloc0 * 128 + cB0);
                ldsm4(Bh[1], slotB + (nloc0 + 16) * 128 + cB1);
                ldsm4(Bl[0], slotB + 32768 + nloc0 * 128 + cB0);
                ldsm4(Bl[1], slotB + 32768 + (nloc0 + 16) * 128 + cB1);
#pragma unroll
                for (int ni = 0; ni < 4; ni++) {
                    const uint32_t* bh = &Bh[ni >> 1][(ni & 1) * 2];
                    const uint32_t* bl = &Bl[ni >> 1][(ni & 1) * 2];
                    mma16816(D0[ni], Ah, bh);
                    mma16816(D1[ni], Ah, bl);
                    mma16816(D1[ni], Al, bh);
                }
            }
            __syncthreads();
            if (g + 2 < 24 && t == 0) {
                const int ng = g + 2;
                uint32_t mb = MB + slot * 8;
                mbar_expect_tx(mb, SLOT_BYTES);
                tma3d(sbase + slot * SLOT_BYTES, &tmW,
                      (ng & 3) * 64, 0, (ng >> 2) * 2, mb);
            }
        }

        const float* bias = (L == 0) ? b0 : (L == 1) ? b1 : (L == 2) ? b2
                          : (L == 3) ? b3 : (L == 4) ? b4 : bp;
        if (L < 5) {
            const uint32_t actNxt = sbase + ((L & 1) ? SM_ACT0 : SM_ACT1);
#pragma unroll
            for (int ni = 0; ni < 4; ni++) {
                int n = wid * 32 + ni * 8 + ccol2;
                float b0v = __ldg(&bias[n]);
                float b1v = __ldg(&bias[n + 1]);
                const uint32_t cN = n >> 3;
                const uint32_t intra = (n & 7) * 2;
#pragma unroll
                for (int hh = 0; hh < 2; hh++) {
                    float d0 = fmaf(D1[ni][hh * 2],     SC_L, D0[ni][hh * 2]);
                    float d1 = fmaf(D1[ni][hh * 2 + 1], SC_L, D0[ni][hh * 2 + 1]);
                    float y0 = fmaxf(d0 + b0v, 0.0f);
                    float y1 = fmaxf(d1 + b1v, 0.0f);
                    __half h0, l0, h1, l1;
                    split2(y0, h0, l0);
                    split2(y1, h1, l1);
                    const int m = crow + hh * 8;
                    uint32_t off = m * 512 + swz(cN, m & 7) * 16 + intra;
                    *(uint32_t*)((char*)smem + (actNxt - sbase) + off) = pack2(h0, h1);
                    *(uint32_t*)((char*)smem + (actNxt - sbase) + 8192 + off) = pack2(l0, l1);
                }
            }
            __syncthreads();
        } else {
#pragma unroll
            for (int ni = 0; ni < 4; ni++) {
                int n = wid * 32 + ni * 8 + ccol2;
                float b0v = __ldg(&bias[n]);
                float b1v = __ldg(&bias[n + 1]);
#pragma unroll
                for (int hh = 0; hh < 2; hh++) {
                    float d0 = fmaf(D1[ni][hh * 2],     SC_L, D0[ni][hh * 2]);
                    float d1 = fmaf(D1[ni][hh * 2 + 1], SC_L, D0[ni][hh * 2 + 1]);
                    const int m = m0 + crow + hh * 8;
                    float2 v;
                    v.x = d0 + b0v + 0.5f;
                    v.y = d1 + b1v + 0.5f;
                    *(float2*)(g_mu + m * 256 + n) = v;
                }
            }
        }
    }
}

// ---------------------------------------------------------------------------
// Fused tail: one CTA per batch row b; thread = (n, s), tid = 2n + s.
// Packed f32x2 m-loop; scalar two-chain accumulation (no repacking).
// ---------------------------------------------------------------------------
__global__ __launch_bounds__(256) void tail_kernel(
    const float* __restrict__ realPoints,
    const float* __restrict__ predMu,
    const float* __restrict__ predScale,
    const float* __restrict__ eps,
    float* __restrict__ out)
{
    const int b = blockIdx.x;
    __shared__ __align__(16) float pkArr[256];   // {nm0_2p, nm0_2p+1, nm1_2p, nm1_2p+1}
    __shared__ __align__(16) float acArr[256];   // {am2_2p, am2_2p+1, cm2_2p, cm2_2p+1}
    __shared__ float sc[7];

    const int tid = threadIdx.x;
    if (tid < 64) {
        float4 v = *(const float4*)(g_mu + b * 256 + tid * 4);
        ((float4*)pkArr)[tid] = make_float4(-v.x, -v.z, -v.y, -v.w);
        float devA = 0.001f + (float)(2 * tid)     * (0.009f / 127.0f);
        float devB = 0.001f + (float)(2 * tid + 1) * (0.009f / 127.0f);
        ((float4*)acArr)[tid] = make_float4(
            (-0.5f / (devA * devA)) * LOG2E_F,
            (-0.5f / (devB * devB)) * LOG2E_F,
            (-2.0f * logf(devA) - LOG2PI_F) * LOG2E_F,
            (-2.0f * logf(devB) - LOG2PI_F) * LOG2E_F);
    }
    if (tid == 0) {
        sc[0] = realPoints[b * 2];
        sc[1] = realPoints[b * 2 + 1];
        sc[2] = predMu[b * 2];
        sc[3] = predMu[b * 2 + 1];
        float p0 = predScale[b * 2], p1 = predScale[b * 2 + 1];
        sc[4] = 1.0f / p0;
        sc[5] = 1.0f / p1;
        sc[6] = logf(p0) + logf(p1);
    }
    __syncthreads();

    const int n = tid >> 1;
    const int s = tid & 1;
    const int pkIdx0 = (n >> 1) * 4 + (n & 1);
    const int pkIdx1 = pkIdx0 + 2;

    const float mu0 = -pkArr[pkIdx0];
    const float mu1 = -pkArr[pkIdx1];
    const float dev = 0.001f + (float)n * (0.009f / 127.0f);

    const int eoff = s * (BSZ * NPTS * 2) + (b * NPTS + n) * 2;
    const float e0 = eps[eoff];
    const float e1 = eps[eoff + 1];
    const float s0 = fmaf(dev, e0, mu0);
    const float s1 = fmaf(dev, e1, mu1);

    {
        long so = ((long)(s * NPTS + n) * BSZ + b) * 2;
        out[OFF_SAMPLED + so]     = s0;
        out[OFF_SAMPLED + so + 1] = s1;
    }

    // lossB: packed f32x2 loop over 64 m-pairs; scalar two-chain accumulation
    const ulonglong2* pk2 = (const ulonglong2*)pkArr;
    const ulonglong2* ac2 = (const ulonglong2*)acArr;
    const u64 s0p = packf2(s0, s0);
    const u64 s1p = packf2(s1, s1);
    float sLo = 0.0f, sHi = 0.0f;
#pragma unroll 8
    for (int p = 0; p < 64; p++) {
        ulonglong2 nm = pk2[p];
        ulonglong2 ac = ac2[p];
        u64 d0 = add2(s0p, nm.x);
        u64 d1 = add2(s1p, nm.y);
        u64 ss = fma2(d1, d1, mul2(d0, d0));
        u64 ar = fma2(ss, ac.x, ac.y);
        float alo, ahi;
        unpackf2(ar, alo, ahi);
        sLo += ex2f(alo);
        sHi += ex2f(ahi);
    }
    float sumexp = sLo + sHi;

    // diag term (same IEEE ops as one f32x2 lane of the loop)
    const float am2n = acArr[pkIdx0];
    const float cm2n = acArr[pkIdx1];
    {
        float d0 = s0 + pkArr[pkIdx0];
        float d1 = s1 + pkArr[pkIdx1];
        float ssn = fmaf(d1, d1, d0 * d0);
        float en = ex2f(fmaf(ssn, am2n, cm2n));
        float lbv = 1.0f - en / sumexp;
        out[OFF_LOSSB + b * 256 + tid] = lbv * lbv;
    }

    float z0 = (s0 - sc[2]) * sc[4];
    float z1 = (s1 - sc[3]) * sc[5];
    float lp = fmaf(-0.5f, fmaf(z0, z0, z1 * z1), -sc[6] - LOG2PI_F);
    float gl  = 1.0f / (1.0f + __expf(-lp));
    float sgn = 1.0f / (1.0f + __expf(lp));
    float tA  = LOG1P_HALF - log1pf(sgn);
    tA *= tA;

    float gl_o = __shfl_xor_sync(0xffffffffu, gl, 1);
    float tA_o = __shfl_xor_sync(0xffffffffu, tA, 1);

    if (s == 0) {
        float glm   = 0.5f * (gl + gl_o);
        float lossA = 0.5f * (tA + tA_o);
        float dr0 = sc[0] - mu0;
        float dr1 = sc[1] - mu1;
        float ssr = fmaf(dr1, dr1, dr0 * dr0);
        float rl  = 1.0f / (1.0f + ex2f(-fmaf(ssr, am2n, cm2n)));
        out[OFF_REAL  + b * NPTS + n] = rl;
        out[OFF_LOSSA + b * NPTS + n] = lossA;
        out[OFF_GEN   + b * NPTS + n] = glm * (1.0f - rl);
    }
}

// ---------------------------------------------------------------------------
typedef CUresult (*encode_fn_t)(
    CUtensorMap*, CUtensorMapDataType, cuuint32_t, void*,
    const cuuint64_t*, const cuuint64_t*, const cuuint32_t*, const cuuint32_t*,
    CUtensorMapInterleave, CUtensorMapSwizzle, CUtensorMapL2promotion,
    CUtensorMapFloatOOBfill);

extern "C" void kernel_launch(void* const* d_in, const int* in_sizes, int n_in,
                              void* d_out, int out_size) {
    const float* latents    = (const float*)d_in[0];
    const float* realPoints = (const float*)d_in[1];
    const float* predMu     = (const float*)d_in[2];
    const float* predScale  = (const float*)d_in[3];
    const float* eps        = (const float*)d_in[4];
    const float* W[5]  = {(const float*)d_in[5],  (const float*)d_in[7],
                          (const float*)d_in[9],  (const float*)d_in[11],
                          (const float*)d_in[13]};
    const float* bb[5] = {(const float*)d_in[6],  (const float*)d_in[8],
                          (const float*)d_in[10], (const float*)d_in[12],
                          (const float*)d_in[14]};
    const float* bp = (const float*)d_in[16];
    float* out = (float*)d_out;

    __half *gA, *gW;
    cudaGetSymbolAddress((void**)&gA, g_Act);
    cudaGetSymbolAddress((void**)&gW, g_Wsplit);

    void* fptr = nullptr;
    cudaDriverEntryPointQueryResult qr;
    cudaGetDriverEntryPoint("cuTensorMapEncodeTiled", &fptr,
                            cudaEnableDefault, &qr);
    encode_fn_t enc = (encode_fn_t)fptr;
    CUtensorMap tmW;
    {
        cuuint64_t dims[3]    = {256, 256, 12};
        cuuint64_t strides[2] = {512, 131072};
        cuuint32_t box[3]     = {64, 256, 2};
        cuuint32_t es[3]      = {1, 1, 1};
        enc(&tmW, CU_TENSOR_MAP_DATA_TYPE_FLOAT16, 3, gW, dims, strides, box, es,
            CU_TENSOR_MAP_INTERLEAVE_NONE, CU_TENSOR_MAP_SWIZZLE_128B,
            CU_TENSOR_MAP_L2_PROMOTION_L2_128B, CU_TENSOR_MAP_FLOAT_OOB_FILL_NONE);
    }

    cudaFuncSetAttribute(mlp6_kernel,
                         cudaFuncAttributeMaxDynamicSharedMemorySize, SM_TOTAL);

    prep_kernel<<<448, 256>>>(W[0], W[1], W[2], W[3], W[4],
                              (const float*)d_in[15], latents, gA);

    mlp6_kernel<<<64, 256, SM_TOTAL>>>(tmW, gA, bb[0], bb[1], bb[2],
                                       bb[3], bb[4], bp);

    tail_kernel<<<BSZ, 256>>>(realPoints, predMu, predScale, eps, out);
}